// round 3
// baseline (speedup 1.0000x reference)
#include <cuda_runtime.h>
#include <cuda_bf16.h>
#include <cstdint>

#define NUM_CLASSES 1000
#define FEAT_DIM    256
#define N_ROWS      262144
#define ALPHA       0.5f

// Scratch accumulators (device globals — no allocation allowed).
__device__ __align__(16) float g_sums[NUM_CLASSES * FEAT_DIM];
__device__ float g_counts[NUM_CLASSES];

// ---------------------------------------------------------------------------
// Kernel 1: zero the accumulators (must run every graph replay).
// ---------------------------------------------------------------------------
__global__ void zero_kernel() {
    int i = blockIdx.x * blockDim.x + threadIdx.x;
    int total = NUM_CLASSES * FEAT_DIM + NUM_CLASSES;
    if (i < NUM_CLASSES * FEAT_DIM) {
        g_sums[i] = 0.0f;
    } else if (i < total) {
        g_counts[i - NUM_CLASSES * FEAT_DIM] = 0.0f;
    }
}

// ---------------------------------------------------------------------------
// Kernel 2: scatter-add. One warp per row. Each lane handles one float4
// column-group; 32 lanes x 4 floats x 2 iters = 256 cols. Vectorized RED
// (red.global.add.v4.f32) cuts L2 atomic op count 4x vs scalar atomicAdd.
// ---------------------------------------------------------------------------
__device__ __forceinline__ void red_add_v4(float* addr, float4 v) {
    asm volatile("red.global.add.v4.f32 [%0], {%1, %2, %3, %4};"
                 :: "l"(addr), "f"(v.x), "f"(v.y), "f"(v.z), "f"(v.w)
                 : "memory");
}

__global__ void accum_kernel(const float* __restrict__ features,
                             const int* __restrict__ labels) {
    int warp_global = (blockIdx.x * blockDim.x + threadIdx.x) >> 5;
    int lane = threadIdx.x & 31;
    if (warp_global >= N_ROWS) return;

    int row = warp_global;
    int cls = labels[row];

    const float4* frow = reinterpret_cast<const float4*>(features + (size_t)row * FEAT_DIM);
    float* srow = g_sums + (size_t)cls * FEAT_DIM;

#pragma unroll
    for (int it = 0; it < 2; it++) {
        int c4 = lane + it * 32;           // float4 index within the row (0..63)
        float4 v = frow[c4];
        red_add_v4(srow + c4 * 4, v);
    }
    if (lane == 0) {
        atomicAdd(&g_counts[cls], 1.0f);
    }
}

// ---------------------------------------------------------------------------
// Kernel 3: finalize — EMA update for classes present in the batch.
// ---------------------------------------------------------------------------
__global__ void finalize_kernel(const float* __restrict__ centers,
                                float* __restrict__ out) {
    int i = blockIdx.x * blockDim.x + threadIdx.x;
    if (i >= NUM_CLASSES * FEAT_DIM) return;
    int cls = i >> 8;  // FEAT_DIM = 256
    float cnt = g_counts[cls];
    float c = centers[i];
    float result = c;
    if (cnt > 0.0f) {
        float mean = g_sums[i] / cnt;
        result = (1.0f - ALPHA) * c + ALPHA * mean;
    }
    out[i] = result;
}

// ---------------------------------------------------------------------------
// Launch: inputs per metadata order: features f32, labels i32, centers f32.
// ---------------------------------------------------------------------------
extern "C" void kernel_launch(void* const* d_in, const int* in_sizes, int n_in,
                              void* d_out, int out_size) {
    const float* features = (const float*)d_in[0];
    const int* labels     = (const int*)d_in[1];
    const float* centers  = (const float*)d_in[2];
    float* out            = (float*)d_out;

    {
        int total = NUM_CLASSES * FEAT_DIM + NUM_CLASSES;
        int threads = 256;
        int blocks = (total + threads - 1) / threads;
        zero_kernel<<<blocks, threads>>>();
    }
    {
        // one warp per row: N_ROWS warps, 8 warps (256 threads) per block
        int threads = 256;
        int blocks = N_ROWS / 8;  // 262144 / 8 = 32768
        accum_kernel<<<blocks, threads>>>(features, labels);
    }
    {
        int total = NUM_CLASSES * FEAT_DIM;
        int threads = 256;
        int blocks = (total + threads - 1) / threads;
        finalize_kernel<<<blocks, threads>>>(centers, out);
    }
}